// round 1
// baseline (speedup 1.0000x reference)
#include <cuda_runtime.h>
#include <cuda_bf16.h>

// Problem shape (fixed by the dataset): [B=32, C=1, H=1024, W=1024] fp32.
#define B_DIM 32
#define HW (1024 * 1024)
#define HW4 (HW / 4)
#define LAMBDA 0.1

// Global accumulators: [0]=diff2, [1]=G2, [2]=H2
__device__ double g_acc[3];

__global__ void init_kernel() {
    if (threadIdx.x < 3) g_acc[threadIdx.x] = 0.0;
}

__global__ __launch_bounds__(256) void praloss_main_kernel(
    const float4* __restrict__ est, const float4* __restrict__ gt)
{
    const int pix4 = blockIdx.x * blockDim.x + threadIdx.x;  // 0 .. HW4-1

    float4 s_e = make_float4(0.f, 0.f, 0.f, 0.f);
    float4 s_g = make_float4(0.f, 0.f, 0.f, 0.f);
    float4 q_e = make_float4(0.f, 0.f, 0.f, 0.f);
    float4 q_d = make_float4(0.f, 0.f, 0.f, 0.f);

    #pragma unroll 8
    for (int b = 0; b < B_DIM; b++) {
        const float4 e = est[(long)b * HW4 + pix4];
        const float4 g = gt [(long)b * HW4 + pix4];
        s_e.x += e.x; s_e.y += e.y; s_e.z += e.z; s_e.w += e.w;
        s_g.x += g.x; s_g.y += g.y; s_g.z += g.z; s_g.w += g.w;
        q_e.x = fmaf(e.x, e.x, q_e.x);
        q_e.y = fmaf(e.y, e.y, q_e.y);
        q_e.z = fmaf(e.z, e.z, q_e.z);
        q_e.w = fmaf(e.w, e.w, q_e.w);
        float dx = e.x - g.x, dy = e.y - g.y, dz = e.z - g.z, dw = e.w - g.w;
        q_d.x = fmaf(dx, dx, q_d.x);
        q_d.y = fmaf(dy, dy, q_d.y);
        q_d.z = fmaf(dz, dz, q_d.z);
        q_d.w = fmaf(dw, dw, q_d.w);
    }

    float diff2 = q_d.x + q_d.y + q_d.z + q_d.w;
    float G2    = q_e.x + q_e.y + q_e.z + q_e.w;
    float H2    = (s_e.x > s_g.x ? q_e.x : 0.f)
                + (s_e.y > s_g.y ? q_e.y : 0.f)
                + (s_e.z > s_g.z ? q_e.z : 0.f)
                + (s_e.w > s_g.w ? q_e.w : 0.f);

    // Warp reduce
    #pragma unroll
    for (int off = 16; off > 0; off >>= 1) {
        diff2 += __shfl_down_sync(0xFFFFFFFFu, diff2, off);
        G2    += __shfl_down_sync(0xFFFFFFFFu, G2,    off);
        H2    += __shfl_down_sync(0xFFFFFFFFu, H2,    off);
    }

    // Block reduce via shared memory (8 warps per 256-thread block)
    __shared__ float sm[3][8];
    const int lane = threadIdx.x & 31;
    const int wid  = threadIdx.x >> 5;
    if (lane == 0) {
        sm[0][wid] = diff2; sm[1][wid] = G2; sm[2][wid] = H2;
    }
    __syncthreads();
    if (wid == 0) {
        float v0 = (lane < 8) ? sm[0][lane] : 0.f;
        float v1 = (lane < 8) ? sm[1][lane] : 0.f;
        float v2 = (lane < 8) ? sm[2][lane] : 0.f;
        #pragma unroll
        for (int off = 4; off > 0; off >>= 1) {
            v0 += __shfl_down_sync(0xFFFFFFFFu, v0, off);
            v1 += __shfl_down_sync(0xFFFFFFFFu, v1, off);
            v2 += __shfl_down_sync(0xFFFFFFFFu, v2, off);
        }
        if (lane == 0) {
            atomicAdd(&g_acc[0], (double)v0);
            atomicAdd(&g_acc[1], (double)v1);
            atomicAdd(&g_acc[2], (double)v2);
        }
    }
}

__global__ void final_kernel(float* __restrict__ out) {
    if (threadIdx.x == 0) {
        double diff2 = g_acc[0];
        double G2    = g_acc[1];
        double H2    = g_acc[2];
        out[0] = (float)(diff2 / G2 + LAMBDA * (diff2 / H2));
    }
}

extern "C" void kernel_launch(void* const* d_in, const int* in_sizes, int n_in,
                              void* d_out, int out_size) {
    const float4* est = (const float4*)d_in[0];
    const float4* gt  = (const float4*)d_in[1];
    float* out = (float*)d_out;

    init_kernel<<<1, 32>>>();
    praloss_main_kernel<<<HW4 / 256, 256>>>(est, gt);
    final_kernel<<<1, 32>>>(out);
}